// round 12
// baseline (speedup 1.0000x reference)
#include <cuda_runtime.h>
#include <cuda_bf16.h>
#include <stdint.h>
#include <math.h>

#define BSZ 64
#define NAG 512
#define OBS 128
#define HID 256
#define MSG 128
#define NACT 16
#define ROWS (BSZ*NAG)   // 32768

// ---------------- scratch (device globals) ----------------
__device__ __align__(16) __nv_bfloat16 g_enc_h[(size_t)ROWS*HID],  g_enc_l[(size_t)ROWS*HID];
__device__ __align__(16) __nv_bfloat16 g_msgq_h[(size_t)ROWS*256], g_msgq_l[(size_t)ROWS*256]; // 0-127 msg, 128-255 Q(scaled)
__device__ __align__(16) __nv_bfloat16 g_ks_h[(size_t)ROWS*MSG],   g_ks_l[(size_t)ROWS*MSG];   // K scaled by imp
__device__ __align__(16) __nv_bfloat16 g_obs_h[(size_t)ROWS*OBS],  g_obs_l[(size_t)ROWS*OBS];
__device__ __align__(16) __nv_bfloat16 g_obss_h[(size_t)ROWS*OBS], g_obss_l[(size_t)ROWS*OBS]; // scaled sqrt(.5)/nrm
__device__ float g_imp[ROWS];
__device__ __align__(16) __nv_bfloat16 g_vT_h[(size_t)BSZ*MSG*NAG], g_vT_l[(size_t)BSZ*MSG*NAG]; // [b][d][k]
__device__ __align__(16) __nv_bfloat16 g_agg_h[(size_t)ROWS*MSG],  g_agg_l[(size_t)ROWS*MSG];
__device__ float g_x[(size_t)ROWS*HID];
__device__ float g_bcat[256];
__device__ float g_bkv[256];
__device__ __align__(16) __nv_bfloat16 g_WeT_h[256*128],  g_WeT_l[256*128];
__device__ __align__(16) __nv_bfloat16 g_WcatT_h[256*256],g_WcatT_l[256*256];
__device__ __align__(16) __nv_bfloat16 g_WkvT_h[256*128], g_WkvT_l[256*128];
__device__ __align__(16) __nv_bfloat16 g_WpT_h[256*384],  g_WpT_l[256*384];

// ---------------- helpers ----------------
__device__ __forceinline__ void bsplit(float x, __nv_bfloat16& h, __nv_bfloat16& l){
    h = __float2bfloat16(x);
    l = __float2bfloat16(x - __bfloat162float(h));
}
__device__ __forceinline__ uint32_t smem_u32(const void* p){
    uint32_t a;
    asm("{ .reg .u64 t; cvta.to.shared.u64 t, %1; cvt.u32.u64 %0, t; }" : "=r"(a) : "l"(p));
    return a;
}
__device__ __forceinline__ void cpa16(uint32_t d, const void* s){
    asm volatile("cp.async.cg.shared.global [%0], [%1], 16;" :: "r"(d), "l"(s));
}
__device__ __forceinline__ void cpa_commit(){ asm volatile("cp.async.commit_group;" ::: "memory"); }
__device__ __forceinline__ void cpa_wait0(){ asm volatile("cp.async.wait_group 0;" ::: "memory"); }
__device__ __forceinline__ void cpa_wait1(){ asm volatile("cp.async.wait_group 1;" ::: "memory"); }
__device__ __forceinline__ void cpa_wait2(){ asm volatile("cp.async.wait_group 2;" ::: "memory"); }
__device__ __forceinline__ void ldsm4(uint32_t* r, uint32_t a){
    asm volatile("ldmatrix.sync.aligned.m8n8.x4.shared.b16 {%0,%1,%2,%3}, [%4];"
        : "=r"(r[0]), "=r"(r[1]), "=r"(r[2]), "=r"(r[3]) : "r"(a));
}
__device__ __forceinline__ void mma16816(float* d, const uint32_t* a, const uint32_t* b){
    asm volatile(
        "mma.sync.aligned.m16n8k16.row.col.f32.bf16.bf16.f32 "
        "{%0,%1,%2,%3}, {%4,%5,%6,%7}, {%8,%9}, {%0,%1,%2,%3};"
        : "+f"(d[0]), "+f"(d[1]), "+f"(d[2]), "+f"(d[3])
        : "r"(a[0]), "r"(a[1]), "r"(a[2]), "r"(a[3]), "r"(b[0]), "r"(b[1]));
}
__device__ __forceinline__ uint32_t packbf2(float x, float y){
    __nv_bfloat162 p; p.x = __float2bfloat16(x); p.y = __float2bfloat16(y);
    return *(uint32_t*)&p;
}

// stage one [128 rows][64 k] bf16 tile, SW128 swizzle, cp.async — 256 threads, 4x16B each
__device__ __forceinline__ void stage_tile(uint32_t smA, const __nv_bfloat16* g, int ld,
                                           int row0, int k0, int tid)
{
    int r = tid >> 1, s0 = (tid & 1) * 4;
    const __nv_bfloat16* src = g + (long long)(row0 + r) * ld + k0 + s0 * 8;
    uint32_t offb = (uint32_t)(r * 128 + s0 * 16);
    #pragma unroll
    for (int j = 0; j < 4; j++){
        uint32_t off = offb + j * 16;
        uint32_t sw = off ^ ((off >> 3) & 0x70u);
        cpa16(smA + sw, src + j * 8);
    }
}
// [rows = nthreads/4][64 k] tile, each thread 2x16B (with 256 threads: 64 rows)
__device__ __forceinline__ void stage_tile512(uint32_t smA, const __nv_bfloat16* g, int ld,
                                              int row0, int k0, int tid)
{
    int r = tid >> 2, s0 = (tid & 3) * 2;
    const __nv_bfloat16* src = g + (long long)(row0 + r) * ld + k0 + s0 * 8;
    uint32_t offb = (uint32_t)(r * 128 + s0 * 16);
    #pragma unroll
    for (int j = 0; j < 2; j++){
        uint32_t off = offb + j * 16;
        uint32_t sw = off ^ ((off >> 3) & 0x70u);
        cpa16(smA + sw, src + j * 8);
    }
}

struct OutD {
    float* f;
    __nv_bfloat16* h;
    __nv_bfloat16* l;
    const float* rowscale;
    float factor;
    int ldc;
    int colsub;
    int relu;
    int vtrans;      // write transposed into [b][d][512] hi/lo
    long long sC;
};

#define SMEM_FLASH 196608          // 2 S-stages (128KB) + V (64KB)
#define GSTG 49152                 // gemm stage: A hi/lo 32KB + B hi/lo 16KB
#define SMEM_GEMM (2*GSTG)         // 98304 -> 2 CTAs/SM

// ================= dense GEMM: 256 threads, 8 warps, warp 32x32, block 128x64, 2-stage =================
__global__ __launch_bounds__(256, 2)
void bf_gemm(const __nv_bfloat16* __restrict__ Ah1, const __nv_bfloat16* __restrict__ Al1, int lda1, int K1,
             const __nv_bfloat16* __restrict__ Ah2, const __nv_bfloat16* __restrict__ Al2, int lda2, int Ktot,
             const __nv_bfloat16* __restrict__ Bh,  const __nv_bfloat16* __restrict__ Bl,  int ldb,
             const float* __restrict__ bias, long long sA1, long long sB,
             int split, OutD o0, OutD o1)
{
    extern __shared__ __align__(1024) char smraw[];
    const uint32_t smb = smem_u32(smraw);
    const int tid = threadIdx.x, wid = tid >> 5, lane = tid & 31;
    const int wm = wid >> 1, wn = wid & 1;
    const int row0 = blockIdx.y * 128, col0 = blockIdx.x * 64;
    const int z = blockIdx.z;
    Ah1 += (long long)z * sA1; Al1 += (long long)z * sA1;
    Bh  += (long long)z * sB;  Bl  += (long long)z * sB;

    const int arow = ((lane >> 3) & 1) * 8 + (lane & 7);
    const int ak8  = ((lane >> 4) & 1) * 8;
    const int brow = ((lane >> 4) & 1) * 8 + (lane & 7);
    const int bk8  = ((lane >> 3) & 1) * 8;

    float acc[2][4][4];
    #pragma unroll
    for (int i = 0; i < 2; i++)
        #pragma unroll
        for (int j = 0; j < 4; j++)
            #pragma unroll
            for (int k = 0; k < 4; k++) acc[i][j][k] = 0.f;

    const int T = Ktot / 64;
    auto do_stage = [&](int t, int buf){
        int k0 = t * 64;
        const __nv_bfloat16 *h, *l; int ld, ka;
        if (k0 < K1){ h = Ah1; l = Al1; ld = lda1; ka = k0; }
        else        { h = Ah2; l = Al2; ld = lda2; ka = k0 - K1; }
        uint32_t sb = smb + buf * GSTG;
        stage_tile(sb + 0,      h,  ld,  row0, ka, tid);       // A hi, 128 rows
        stage_tile(sb + 16384,  l,  ld,  row0, ka, tid);       // A lo
        stage_tile512(sb + 32768, Bh, ldb, col0, k0, tid);     // B hi, 64 rows
        stage_tile512(sb + 40960, Bl, ldb, col0, k0, tid);     // B lo
        cpa_commit();
    };

    do_stage(0, 0);
    for (int t = 0; t < T; t++){
        if (t + 1 < T){ do_stage(t + 1, (t + 1) & 1); cpa_wait1(); }
        else          { cpa_wait0(); }
        __syncthreads();
        uint32_t sm = smb + (t & 1) * GSTG;
        #pragma unroll
        for (int ks = 0; ks < 4; ks++){
            const int kk = ks * 16;
            uint32_t ah[2][4], al[2][4], bh[4][2], bl[4][2], t4[4];
            #pragma unroll
            for (int mt = 0; mt < 2; mt++){
                uint32_t off = (uint32_t)((wm*32 + mt*16 + arow) * 128 + (kk + ak8) * 2);
                uint32_t sw = off ^ ((off >> 3) & 0x70u);
                ldsm4(ah[mt], sm + 0     + sw);
                ldsm4(al[mt], sm + 16384 + sw);
            }
            #pragma unroll
            for (int np = 0; np < 2; np++){
                uint32_t off = (uint32_t)((wn*32 + np*16 + brow) * 128 + (kk + bk8) * 2);
                uint32_t sw = off ^ ((off >> 3) & 0x70u);
                ldsm4(t4, sm + 32768 + sw);
                bh[np*2][0]=t4[0]; bh[np*2][1]=t4[1]; bh[np*2+1][0]=t4[2]; bh[np*2+1][1]=t4[3];
                ldsm4(t4, sm + 40960 + sw);
                bl[np*2][0]=t4[0]; bl[np*2][1]=t4[1]; bl[np*2+1][0]=t4[2]; bl[np*2+1][1]=t4[3];
            }
            #pragma unroll
            for (int mt = 0; mt < 2; mt++)
                #pragma unroll
                for (int nt = 0; nt < 4; nt++){
                    mma16816(acc[mt][nt], ah[mt], bh[nt]);
                    mma16816(acc[mt][nt], ah[mt], bl[nt]);
                    mma16816(acc[mt][nt], al[mt], bh[nt]);
                }
        }
        __syncthreads();
    }

    const OutD& od = (blockIdx.x < split) ? o0 : o1;
    const int lq = lane >> 2, le = (lane & 3) * 2;
    #pragma unroll
    for (int mt = 0; mt < 2; mt++){
        int gr0 = row0 + wm*32 + mt*16 + lq;
        float rs0 = od.rowscale ? od.rowscale[gr0]   * od.factor : od.factor;
        float rs1 = od.rowscale ? od.rowscale[gr0+8] * od.factor : od.factor;
        #pragma unroll
        for (int nt = 0; nt < 4; nt++){
            int gc = col0 + wn*32 + nt*8 + le;
            float b0 = bias ? bias[gc] : 0.f, b1 = bias ? bias[gc+1] : 0.f;
            float v00 = (acc[mt][nt][0] + b0) * rs0, v01 = (acc[mt][nt][1] + b1) * rs0;
            float v10 = (acc[mt][nt][2] + b0) * rs1, v11 = (acc[mt][nt][3] + b1) * rs1;
            if (od.relu){
                v00 = fmaxf(v00, 0.f); v01 = fmaxf(v01, 0.f);
                v10 = fmaxf(v10, 0.f); v11 = fmaxf(v11, 0.f);
            }
            if (od.vtrans){
                int d = gc - od.colsub;
                int bidx = gr0 >> 9, kt0 = gr0 & 511;
                long long o00 = ((long long)bidx * MSG + d) * NAG + kt0;
                __nv_bfloat16 h, l;
                bsplit(v00, h, l); od.h[o00]           = h; od.l[o00]           = l;
                bsplit(v01, h, l); od.h[o00 + NAG]     = h; od.l[o00 + NAG]     = l;
                bsplit(v10, h, l); od.h[o00 + 8]       = h; od.l[o00 + 8]       = l;
                bsplit(v11, h, l); od.h[o00 + NAG + 8] = h; od.l[o00 + NAG + 8] = l;
                continue;
            }
            long long i0 = od.sC * z + (long long)gr0 * od.ldc + (gc - od.colsub);
            long long i1 = od.sC * z + (long long)(gr0 + 8) * od.ldc + (gc - od.colsub);
            if (od.f){
                *(float2*)(od.f + i0) = make_float2(v00, v01);
                *(float2*)(od.f + i1) = make_float2(v10, v11);
            }
            if (od.h){
                __nv_bfloat162 ph, pl;
                bsplit(v00, ph.x, pl.x); bsplit(v01, ph.y, pl.y);
                *(__nv_bfloat162*)(od.h + i0) = ph; *(__nv_bfloat162*)(od.l + i0) = pl;
                bsplit(v10, ph.x, pl.x); bsplit(v11, ph.y, pl.y);
                *(__nv_bfloat162*)(od.h + i1) = ph; *(__nv_bfloat162*)(od.l + i1) = pl;
            }
        }
    }
}

// ================= flash attention: 256 threads, V prefetched under S phase =================
__global__ __launch_bounds__(256, 1)
void flash_kernel(const __nv_bfloat16* __restrict__ Qh, const __nv_bfloat16* __restrict__ Ql,
                  const __nv_bfloat16* __restrict__ Kh, const __nv_bfloat16* __restrict__ Kl,
                  const __nv_bfloat16* __restrict__ Oh, const __nv_bfloat16* __restrict__ Ol,
                  const __nv_bfloat16* __restrict__ Vh, const __nv_bfloat16* __restrict__ Vl,
                  __nv_bfloat16* __restrict__ aggh, __nv_bfloat16* __restrict__ aggl)
{
    extern __shared__ __align__(1024) char smraw[];
    const uint32_t smb = smem_u32(smraw);
    const uint32_t smv = smb + 131072;
    const int tid = threadIdx.x, w = tid >> 5, lane = tid & 31;
    const int q0 = blockIdx.x * 128;
    const int b = blockIdx.y;
    const int gr = b * NAG;
    const long long vbase = (long long)b * MSG * NAG;

    const int arow = ((lane >> 3) & 1) * 8 + (lane & 7);
    const int ak8  = ((lane >> 4) & 1) * 8;
    const int brow = ((lane >> 4) & 1) * 8 + (lane & 7);
    const int bk8  = ((lane >> 3) & 1) * 8;
    const int lq = lane >> 2;

    float O[16][4];
    #pragma unroll
    for (int nt = 0; nt < 16; nt++)
        #pragma unroll
        for (int j = 0; j < 4; j++) O[nt][j] = 0.f;
    float m0 = -1e30f, m1 = -1e30f, sum0 = 0.f, sum1 = 0.f;

    for (int kt = 0; kt < 4; kt++){
        const int k0 = kt * 128;

        float S[16][4];
        #pragma unroll
        for (int nt = 0; nt < 16; nt++)
            #pragma unroll
            for (int j = 0; j < 4; j++) S[nt][j] = 0.f;

        auto do_stage = [&](int t, int buf){
            uint32_t sb = smb + buf * 65536;
            if (t < 2){
                stage_tile(sb + 0,     Qh, 256, gr + q0, t*64, tid);
                stage_tile(sb + 16384, Ql, 256, gr + q0, t*64, tid);
                stage_tile(sb + 32768, Kh, 128, gr + k0, t*64, tid);
                stage_tile(sb + 49152, Kl, 128, gr + k0, t*64, tid);
            } else {
                stage_tile(sb + 0,     Oh, 128, gr + q0, (t-2)*64, tid);
                stage_tile(sb + 16384, Ol, 128, gr + q0, (t-2)*64, tid);
                stage_tile(sb + 32768, Oh, 128, gr + k0, (t-2)*64, tid);
                stage_tile(sb + 49152, Ol, 128, gr + k0, (t-2)*64, tid);
            }
            cpa_commit();
        };

        do_stage(0, 0);
        for (int t = 0; t < 4; t++){
            if (t == 0){
                do_stage(1, 1);
                stage_tile(smv + 0,     Vh + vbase, NAG, 0, k0,      tid);
                stage_tile(smv + 16384, Vl + vbase, NAG, 0, k0,      tid);
                stage_tile(smv + 32768, Vh + vbase, NAG, 0, k0 + 64, tid);
                stage_tile(smv + 49152, Vl + vbase, NAG, 0, k0 + 64, tid);
                cpa_commit();
            } else if (t + 1 < 4){
                do_stage(t + 1, (t + 1) & 1);
            }
            if (t <= 1)      cpa_wait2();
            else if (t == 2) cpa_wait1();
            else             cpa_wait0();
            __syncthreads();
            uint32_t sm = smb + (t & 1) * 65536;
            #pragma unroll
            for (int ks = 0; ks < 4; ks++){
                const int kk = ks * 16;
                uint32_t ah[4], al[4], th[4], tl[4];
                {
                    uint32_t off = (uint32_t)((w*16 + arow) * 128 + (kk + ak8) * 2);
                    uint32_t sw = off ^ ((off >> 3) & 0x70u);
                    ldsm4(ah, sm + 0     + sw);
                    ldsm4(al, sm + 16384 + sw);
                }
                #pragma unroll
                for (int np = 0; np < 8; np++){
                    uint32_t off = (uint32_t)((np*16 + brow) * 128 + (kk + bk8) * 2);
                    uint32_t sw = off ^ ((off >> 3) & 0x70u);
                    ldsm4(th, sm + 32768 + sw);
                    ldsm4(tl, sm + 49152 + sw);
                    uint32_t b0[2] = {th[0], th[1]}, b1[2] = {th[2], th[3]};
                    uint32_t c0[2] = {tl[0], tl[1]}, c1[2] = {tl[2], tl[3]};
                    mma16816(S[np*2],   ah, b0);
                    mma16816(S[np*2],   ah, c0);
                    mma16816(S[np*2],   al, b0);
                    mma16816(S[np*2+1], ah, b1);
                    mma16816(S[np*2+1], ah, c1);
                    mma16816(S[np*2+1], al, b1);
                }
            }
            __syncthreads();
        }

        float mx0 = -1e30f, mx1 = -1e30f;
        #pragma unroll
        for (int nt = 0; nt < 16; nt++){
            mx0 = fmaxf(mx0, fmaxf(S[nt][0], S[nt][1]));
            mx1 = fmaxf(mx1, fmaxf(S[nt][2], S[nt][3]));
        }
        mx0 = fmaxf(mx0, __shfl_xor_sync(0xffffffffu, mx0, 1));
        mx0 = fmaxf(mx0, __shfl_xor_sync(0xffffffffu, mx0, 2));
        mx1 = fmaxf(mx1, __shfl_xor_sync(0xffffffffu, mx1, 1));
        mx1 = fmaxf(mx1, __shfl_xor_sync(0xffffffffu, mx1, 2));
        float M0 = fmaxf(m0, mx0), M1 = fmaxf(m1, mx1);
        float f0 = __expf(m0 - M0), f1 = __expf(m1 - M1);
        float rs0 = 0.f, rs1 = 0.f;
        #pragma unroll
        for (int nt = 0; nt < 16; nt++){
            float p0 = __expf(S[nt][0] - M0); S[nt][0] = p0; rs0 += p0;
            float p1 = __expf(S[nt][1] - M0); S[nt][1] = p1; rs0 += p1;
            float p2 = __expf(S[nt][2] - M1); S[nt][2] = p2; rs1 += p2;
            float p3 = __expf(S[nt][3] - M1); S[nt][3] = p3; rs1 += p3;
        }
        rs0 += __shfl_xor_sync(0xffffffffu, rs0, 1);
        rs0 += __shfl_xor_sync(0xffffffffu, rs0, 2);
        rs1 += __shfl_xor_sync(0xffffffffu, rs1, 1);
        rs1 += __shfl_xor_sync(0xffffffffu, rs1, 2);
        sum0 = sum0 * f0 + rs0;
        sum1 = sum1 * f1 + rs1;
        m0 = M0; m1 = M1;
        #pragma unroll
        for (int nt = 0; nt < 16; nt++){
            O[nt][0] *= f0; O[nt][1] *= f0; O[nt][2] *= f1; O[nt][3] *= f1;
        }

        #pragma unroll
        for (int ks = 0; ks < 8; ks++){
            uint32_t aph[4], apl[4];
            {
                float p00 = S[2*ks][0],   p01 = S[2*ks][1];
                float p10 = S[2*ks][2],   p11 = S[2*ks][3];
                float p20 = S[2*ks+1][0], p21 = S[2*ks+1][1];
                float p30 = S[2*ks+1][2], p31 = S[2*ks+1][3];
                aph[0] = packbf2(p00, p01);
                aph[1] = packbf2(p10, p11);
                aph[2] = packbf2(p20, p21);
                aph[3] = packbf2(p30, p31);
                __nv_bfloat162 h0 = *(__nv_bfloat162*)&aph[0];
                __nv_bfloat162 h1 = *(__nv_bfloat162*)&aph[1];
                __nv_bfloat162 h2 = *(__nv_bfloat162*)&aph[2];
                __nv_bfloat162 h3 = *(__nv_bfloat162*)&aph[3];
                apl[0] = packbf2(p00 - __bfloat162float(h0.x), p01 - __bfloat162float(h0.y));
                apl[1] = packbf2(p10 - __bfloat162float(h1.x), p11 - __bfloat162float(h1.y));
                apl[2] = packbf2(p20 - __bfloat162float(h2.x), p21 - __bfloat162float(h2.y));
                apl[3] = packbf2(p30 - __bfloat162float(h3.x), p31 - __bfloat162float(h3.y));
            }
            uint32_t base = (ks < 4) ? smv : smv + 32768;
            uint32_t basl = base + 16384;
            const int kk = (ks & 3) * 16;
            #pragma unroll
            for (int np = 0; np < 8; np++){
                uint32_t off = (uint32_t)((np*16 + brow) * 128 + (kk + bk8) * 2);
                uint32_t sw = off ^ ((off >> 3) & 0x70u);
                uint32_t th[4], tl[4];
                ldsm4(th, base + sw);
                ldsm4(tl, basl + sw);
                uint32_t b0[2] = {th[0], th[1]}, b1[2] = {th[2], th[3]};
                uint32_t c0[2] = {tl[0], tl[1]}, c1[2] = {tl[2], tl[3]};
                mma16816(O[np*2],   aph, b0);
                mma16816(O[np*2],   aph, c0);
                mma16816(O[np*2],   apl, b0);
                mma16816(O[np*2+1], aph, b1);
                mma16816(O[np*2+1], aph, c1);
                mma16816(O[np*2+1], apl, b1);
            }
        }
        __syncthreads();
    }

    float inv0 = 1.f / sum0, inv1 = 1.f / sum1;
    long long r0 = (long long)(gr + q0 + w*16 + lq) * MSG;
    long long r1 = r0 + 8 * MSG;
    #pragma unroll
    for (int nt = 0; nt < 16; nt++){
        int d = nt*8 + (lane & 3)*2;
        __nv_bfloat162 ph, pl;
        bsplit(O[nt][0] * inv0, ph.x, pl.x);
        bsplit(O[nt][1] * inv0, ph.y, pl.y);
        *(__nv_bfloat162*)(aggh + r0 + d) = ph;
        *(__nv_bfloat162*)(aggl + r0 + d) = pl;
        bsplit(O[nt][2] * inv1, ph.x, pl.x);
        bsplit(O[nt][3] * inv1, ph.y, pl.y);
        *(__nv_bfloat162*)(aggh + r1 + d) = ph;
        *(__nv_bfloat162*)(aggl + r1 + d) = pl;
    }
}

// ---------------- packing kernels ----------------
__global__ void pack_obs(const float* __restrict__ obs,
                         __nv_bfloat16* __restrict__ h, __nv_bfloat16* __restrict__ l)
{
    long long i = (long long)blockIdx.x * 256 + threadIdx.x;
    __nv_bfloat16 hh, ll; bsplit(obs[i], hh, ll);
    h[i] = hh; l[i] = ll;
}
__global__ void pack_we(const float* __restrict__ We,
                        __nv_bfloat16* __restrict__ hi, __nv_bfloat16* __restrict__ lo)
{
    int i = blockIdx.x * 256 + threadIdx.x;
    int n = i >> 7, k = i & 127;
    __nv_bfloat16 h, l; bsplit(We[k*256 + n], h, l);
    hi[i] = h; lo[i] = l;
}
__global__ void pack_wcat(const float* __restrict__ Wc, const float* __restrict__ Wn,
                          const float* __restrict__ Wb, const float* __restrict__ Wq,
                          const float* __restrict__ bc, const float* __restrict__ bn,
                          const float* __restrict__ bbp, const float* __restrict__ bq,
                          __nv_bfloat16* __restrict__ hi, __nv_bfloat16* __restrict__ lo,
                          float* __restrict__ bcat)
{
    int i = blockIdx.x * 256 + threadIdx.x;
    int n = i >> 8, k = i & 255;
    float v;
    if (n < 32)       v = Wc[k*32 + n];
    else if (n < 96)  v = Wn[k*64 + (n-32)];
    else if (n < 128) v = Wb[k*32 + (n-96)];
    else              v = Wq[k*128 + (n-128)];
    __nv_bfloat16 h, l; bsplit(v, h, l);
    hi[i] = h; lo[i] = l;
    if (k == 0)
        bcat[n] = (n < 32) ? bc[n] : (n < 96) ? bn[n-32] : (n < 128) ? bbp[n-96] : bq[n-128];
}
__global__ void pack_wkv(const float* __restrict__ Wk, const float* __restrict__ Wv,
                         const float* __restrict__ bk, const float* __restrict__ bv,
                         __nv_bfloat16* __restrict__ hi, __nv_bfloat16* __restrict__ lo,
                         float* __restrict__ bkv)
{
    int i = blockIdx.x * 256 + threadIdx.x;
    int n = i >> 7, k = i & 127;
    float v = (n < 128) ? Wk[k*128 + n] : Wv[k*128 + (n-128)];
    __nv_bfloat16 h, l; bsplit(v, h, l);
    hi[i] = h; lo[i] = l;
    if (k == 0) bkv[n] = (n < 128) ? bk[n] : bv[n-128];
}
__global__ void pack_wp(const float* __restrict__ Wp,
                        __nv_bfloat16* __restrict__ hi, __nv_bfloat16* __restrict__ lo)
{
    int i = blockIdx.x * 256 + threadIdx.x;
    int n = i / 384, k = i % 384;
    __nv_bfloat16 h, l; bsplit(Wp[k*256 + n], h, l);
    hi[i] = h; lo[i] = l;
}

// ---------------- importance + obs norm + scaled obs pack (fused) ----------------
__global__ void impnorm_kernel(const __nv_bfloat16* __restrict__ eh,
                               const __nv_bfloat16* __restrict__ el,
                               const float* __restrict__ obs,
                               const float* __restrict__ Wi,
                               const float* __restrict__ bi,
                               float* __restrict__ imp,
                               __nv_bfloat16* __restrict__ osh,
                               __nv_bfloat16* __restrict__ osl)
{
    int row = blockIdx.x * 8 + threadIdx.y;
    int lane = threadIdx.x;
    const __nv_bfloat16* ph = eh + (long long)row * HID;
    const __nv_bfloat16* pl = el + (long long)row * HID;
    const float* o = obs + (long long)row * OBS;
    float d = 0.f, ss = 0.f;
    float ov[4];
    #pragma unroll
    for (int i = 0; i < HID/32; i++){
        int k = lane + 32*i;
        float e = __bfloat162float(ph[k]) + __bfloat162float(pl[k]);
        d += e * Wi[k];
    }
    #pragma unroll
    for (int i = 0; i < OBS/32; i++){ ov[i] = o[lane + 32*i]; ss += ov[i]*ov[i]; }
    #pragma unroll
    for (int off = 16; off; off >>= 1){
        d  += __shfl_xor_sync(0xffffffffu, d, off);
        ss += __shfl_xor_sync(0xffffffffu, ss, off);
    }
    if (lane == 0)
        imp[row] = 1.f / (1.f + expf(-(d + bi[0])));
    float s = 0.7071067811865476f / (sqrtf(ss) + 1e-8f);
    #pragma unroll
    for (int i = 0; i < OBS/32; i++){
        int k = lane + 32*i;
        __nv_bfloat16 hh, ll; bsplit(ov[i] * s, hh, ll);
        osh[(long long)row * OBS + k] = hh;
        osl[(long long)row * OBS + k] = ll;
    }
}

// ---------------- head ----------------
__global__ void head_kernel(const float* __restrict__ x,
                            const float* __restrict__ Wa,
                            const float* __restrict__ ba,
                            const float* __restrict__ Wcr,
                            const float* __restrict__ bcr,
                            float* __restrict__ out)
{
    int row = blockIdx.x * 8 + threadIdx.y;
    int lane = threadIdx.x;
    const float* xr = x + (long long)row * HID;
    float xv[8];
    #pragma unroll
    for (int i = 0; i < 8; i++) xv[i] = xr[lane + 32*i];
    #pragma unroll
    for (int j = 0; j < 17; j++){
        float p = 0.f;
        #pragma unroll
        for (int i = 0; i < 8; i++){
            int k = lane + 32*i;
            float w = (j < 16) ? Wa[(long long)k * NACT + j] : Wcr[k];
            p += xv[i] * w;
        }
        #pragma unroll
        for (int off = 16; off; off >>= 1) p += __shfl_down_sync(0xffffffffu, p, off);
        if (lane == 0){
            if (j < 16) out[(long long)row * NACT + j] = p + ba[j];
            else        out[(long long)ROWS * NACT + row] = p + bcr[0];
        }
    }
}

// ---------------- launch ----------------
extern "C" void kernel_launch(void* const* d_in, const int* in_sizes, int n_in,
                              void* d_out, int out_size)
{
    const float* obs = (const float*)d_in[0];
    const float* We  = (const float*)d_in[2];   const float* be  = (const float*)d_in[3];
    const float* Wc  = (const float*)d_in[4];   const float* bc  = (const float*)d_in[5];
    const float* Wn  = (const float*)d_in[6];   const float* bn  = (const float*)d_in[7];
    const float* Wb  = (const float*)d_in[8];   const float* bbp = (const float*)d_in[9];
    const float* Wi  = (const float*)d_in[10];  const float* bi  = (const float*)d_in[11];
    const float* Wq  = (const float*)d_in[12];  const float* bq  = (const float*)d_in[13];
    const float* Wk  = (const float*)d_in[14];  const float* bk  = (const float*)d_in[15];
    const float* Wv  = (const float*)d_in[16];  const float* bv  = (const float*)d_in[17];
    const float* Wp  = (const float*)d_in[18];  const float* bp  = (const float*)d_in[19];
    const float* Wa  = (const float*)d_in[20];  const float* ba  = (const float*)d_in[21];
    const float* Wcr = (const float*)d_in[22];  const float* bcr = (const float*)d_in[23];
    float* out = (float*)d_out;

    #define GA(p, sym) cudaGetSymbolAddress((void**)&p, sym)
    __nv_bfloat16 *ench,*encl,*mqh,*mql,*ksh,*ksl,*obh,*obl,*osh,*osl,*vth,*vtl,*agh,*agl;
    __nv_bfloat16 *WeTh,*WeTl,*WcTh,*WcTl,*WkvTh,*WkvTl,*WpTh,*WpTl;
    float *imp,*xb,*bcat,*bkv;
    GA(ench,g_enc_h); GA(encl,g_enc_l); GA(mqh,g_msgq_h); GA(mql,g_msgq_l);
    GA(ksh,g_ks_h); GA(ksl,g_ks_l); GA(obh,g_obs_h); GA(obl,g_obs_l);
    GA(osh,g_obss_h); GA(osl,g_obss_l);
    GA(vth,g_vT_h); GA(vtl,g_vT_l); GA(agh,g_agg_h); GA(agl,g_agg_l);
    GA(imp,g_imp); GA(xb,g_x);
    GA(bcat,g_bcat); GA(bkv,g_bkv);
    GA(WeTh,g_WeT_h); GA(WeTl,g_WeT_l); GA(WcTh,g_WcatT_h); GA(WcTl,g_WcatT_l);
    GA(WkvTh,g_WkvT_h); GA(WkvTl,g_WkvT_l); GA(WpTh,g_WpT_h); GA(WpTl,g_WpT_l);
    #undef GA

    cudaFuncSetAttribute(bf_gemm,      cudaFuncAttributeMaxDynamicSharedMemorySize, SMEM_GEMM);
    cudaFuncSetAttribute(flash_kernel, cudaFuncAttributeMaxDynamicSharedMemorySize, SMEM_FLASH);

    OutD z = {};

    // packs for first two gemms
    pack_obs <<<ROWS*OBS/256, 256>>>(obs, obh, obl);
    pack_we  <<<128, 256>>>(We, WeTh, WeTl);
    pack_wcat<<<256, 256>>>(Wc, Wn, Wb, Wq, bc, bn, bbp, bq, WcTh, WcTl, bcat);

    // enc = relu(obs @ We + be) -> hi/lo
    {
        OutD o = z; o.h = ench; o.l = encl; o.factor = 1.f; o.ldc = 256; o.relu = 1;
        bf_gemm<<<dim3(4,256,1), 256, SMEM_GEMM>>>(obh, obl, OBS, OBS, nullptr, nullptr, 0, OBS,
                                                   WeTh, WeTl, OBS, be, 0, 0, 4, o, o);
    }
    // imp + scaled obs pack (fused)
    impnorm_kernel<<<ROWS/8, dim3(32,8)>>>(ench, encl, obs, Wi, bi, imp, osh, osl);
    // msgq = enc @ Wcat + bcat; Q (cols>=128) scaled by imp/sqrt(128)
    {
        OutD o0 = z; o0.h = mqh; o0.l = mql; o0.factor = 1.f; o0.ldc = 256;
        OutD o1 = o0; o1.rowscale = imp; o1.factor = 0.08838834764831845f;
        bf_gemm<<<dim3(4,256,1), 256, SMEM_GEMM>>>(ench, encl, 256, 256, nullptr, nullptr, 0, 256,
                                                   WcTh, WcTl, 256, bcat, 0, 0, 2, o0, o1);
    }
    // pack KV weights
    pack_wkv <<<128, 256>>>(Wk, Wv, bk, bv, WkvTh, WkvTl, bkv);
    // kv: K (cols<128) scaled by imp -> hi/lo; V (cols>=128) -> transposed vT hi/lo
    {
        OutD o0 = z; o0.h = ksh; o0.l = ksl; o0.rowscale = imp; o0.factor = 1.f; o0.ldc = 128;
        OutD o1 = z; o1.h = vth; o1.l = vtl; o1.factor = 1.f; o1.colsub = 128; o1.vtrans = 1;
        bf_gemm<<<dim3(4,256,1), 256, SMEM_GEMM>>>(mqh, mql, 256, 128, nullptr, nullptr, 0, 128,
                                                   WkvTh, WkvTl, 128, bkv, 0, 0, 2, o0, o1);
    }
    // pack Wp (independent; fills gap before flash)
    pack_wp  <<<384, 256>>>(Wp, WpTh, WpTl);
    // flash attention -> agg hi/lo
    flash_kernel<<<dim3(4, BSZ), 256, SMEM_FLASH>>>(mqh + 128, mql + 128, ksh, ksl,
                                                    osh, osl, vth, vtl, agh, agl);
    // x = relu([enc|agg] @ Wp + bp) -> fp32
    {
        OutD o = z; o.f = xb; o.factor = 1.f; o.ldc = 256; o.relu = 1;
        bf_gemm<<<dim3(4,256,1), 256, SMEM_GEMM>>>(ench, encl, 256, 256, agh, agl, 128, 384,
                                                   WpTh, WpTl, 384, bp, 0, 0, 4, o, o);
    }
    // heads
    head_kernel<<<ROWS/8, dim3(32,8)>>>(xb, Wa, ba, Wcr, bcr, out);
}

// round 13
// speedup vs baseline: 1.4494x; 1.4494x over previous
#include <cuda_runtime.h>
#include <cuda_fp16.h>
#include <stdint.h>
#include <math.h>

#define BSZ 64
#define NAG 512
#define OBS 128
#define HID 256
#define MSG 128
#define NACT 16
#define ROWS (BSZ*NAG)   // 32768

// ---------------- scratch (device globals, all fp16 single) ----------------
__device__ __align__(16) __half g_enc[(size_t)ROWS*HID];
__device__ __align__(16) __half g_msgq[(size_t)ROWS*256];   // 0-127 msg, 128-255 Q(scaled)
__device__ __align__(16) __half g_ks[(size_t)ROWS*MSG];     // K scaled by imp
__device__ __align__(16) __half g_obs[(size_t)ROWS*OBS];
__device__ __align__(16) __half g_obss[(size_t)ROWS*OBS];   // scaled sqrt(.5)/nrm
__device__ float g_imp[ROWS];
__device__ __align__(16) __half g_vT[(size_t)BSZ*MSG*NAG];  // [b][d][k]
__device__ __align__(16) __half g_agg[(size_t)ROWS*MSG];
__device__ float g_x[(size_t)ROWS*HID];
__device__ float g_bcat[256];
__device__ float g_bkv[256];
__device__ __align__(16) __half g_WeT[256*128];
__device__ __align__(16) __half g_WcatT[256*256];
__device__ __align__(16) __half g_WkvT[256*128];
__device__ __align__(16) __half g_WpT[256*384];

// ---------------- helpers ----------------
__device__ __forceinline__ uint32_t smem_u32(const void* p){
    uint32_t a;
    asm("{ .reg .u64 t; cvta.to.shared.u64 t, %1; cvt.u32.u64 %0, t; }" : "=r"(a) : "l"(p));
    return a;
}
__device__ __forceinline__ void cpa16(uint32_t d, const void* s){
    asm volatile("cp.async.cg.shared.global [%0], [%1], 16;" :: "r"(d), "l"(s));
}
__device__ __forceinline__ void cpa_commit(){ asm volatile("cp.async.commit_group;" ::: "memory"); }
__device__ __forceinline__ void cpa_wait0(){ asm volatile("cp.async.wait_group 0;" ::: "memory"); }
__device__ __forceinline__ void cpa_wait1(){ asm volatile("cp.async.wait_group 1;" ::: "memory"); }
__device__ __forceinline__ void cpa_wait2(){ asm volatile("cp.async.wait_group 2;" ::: "memory"); }
__device__ __forceinline__ void ldsm4(uint32_t* r, uint32_t a){
    asm volatile("ldmatrix.sync.aligned.m8n8.x4.shared.b16 {%0,%1,%2,%3}, [%4];"
        : "=r"(r[0]), "=r"(r[1]), "=r"(r[2]), "=r"(r[3]) : "r"(a));
}
__device__ __forceinline__ void mma16816(float* d, const uint32_t* a, const uint32_t* b){
    asm volatile(
        "mma.sync.aligned.m16n8k16.row.col.f32.f16.f16.f32 "
        "{%0,%1,%2,%3}, {%4,%5,%6,%7}, {%8,%9}, {%0,%1,%2,%3};"
        : "+f"(d[0]), "+f"(d[1]), "+f"(d[2]), "+f"(d[3])
        : "r"(a[0]), "r"(a[1]), "r"(a[2]), "r"(a[3]), "r"(b[0]), "r"(b[1]));
}
__device__ __forceinline__ uint32_t packh2(float x, float y){
    __half2 p; p.x = __float2half_rn(x); p.y = __float2half_rn(y);
    return *(uint32_t*)&p;
}

// stage one [128 rows][64 k] fp16 tile, SW128 swizzle, cp.async — 256 threads, 4x16B each
__device__ __forceinline__ void stage_tile(uint32_t smA, const __half* g, int ld,
                                           int row0, int k0, int tid)
{
    int r = tid >> 1, s0 = (tid & 1) * 4;
    const __half* src = g + (long long)(row0 + r) * ld + k0 + s0 * 8;
    uint32_t offb = (uint32_t)(r * 128 + s0 * 16);
    #pragma unroll
    for (int j = 0; j < 4; j++){
        uint32_t off = offb + j * 16;
        uint32_t sw = off ^ ((off >> 3) & 0x70u);
        cpa16(smA + sw, src + j * 8);
    }
}
// [64 rows][64 k] tile with 256 threads, 2x16B each
__device__ __forceinline__ void stage_tile64(uint32_t smA, const __half* g, int ld,
                                             int row0, int k0, int tid)
{
    int r = tid >> 2, s0 = (tid & 3) * 2;
    const __half* src = g + (long long)(row0 + r) * ld + k0 + s0 * 8;
    uint32_t offb = (uint32_t)(r * 128 + s0 * 16);
    #pragma unroll
    for (int j = 0; j < 2; j++){
        uint32_t off = offb + j * 16;
        uint32_t sw = off ^ ((off >> 3) & 0x70u);
        cpa16(smA + sw, src + j * 8);
    }
}

struct OutD {
    float* f;
    __half* h;
    const float* rowscale;
    float factor;
    int ldc;
    int colsub;
    int relu;
    int vtrans;      // write transposed into [b][d][512]
    long long sC;
};

#define GSTG 24576                 // A 16KB + B 8KB
#define SMEM_GEMM (2*GSTG)         // 49152
#define SMEM_FLASH 98304           // 2 S-stages (64KB) + V (32KB)

// ================= dense GEMM: 256 threads, 8 warps (4x2), block 128x64, 2-stage =================
__global__ __launch_bounds__(256, 2)
void bf_gemm(const __half* __restrict__ A1, int lda1, int K1,
             const __half* __restrict__ A2, int lda2, int Ktot,
             const __half* __restrict__ B, int ldb,
             const float* __restrict__ bias, long long sA1, long long sB,
             int split, OutD o0, OutD o1)
{
    extern __shared__ __align__(1024) char smraw[];
    const uint32_t smb = smem_u32(smraw);
    const int tid = threadIdx.x, wid = tid >> 5, lane = tid & 31;
    const int wm = wid >> 1, wn = wid & 1;
    const int row0 = blockIdx.y * 128, col0 = blockIdx.x * 64;
    const int z = blockIdx.z;
    A1 += (long long)z * sA1;
    B  += (long long)z * sB;

    const int arow = ((lane >> 3) & 1) * 8 + (lane & 7);
    const int ak8  = ((lane >> 4) & 1) * 8;
    const int brow = ((lane >> 4) & 1) * 8 + (lane & 7);
    const int bk8  = ((lane >> 3) & 1) * 8;

    float acc[2][4][4];
    #pragma unroll
    for (int i = 0; i < 2; i++)
        #pragma unroll
        for (int j = 0; j < 4; j++)
            #pragma unroll
            for (int k = 0; k < 4; k++) acc[i][j][k] = 0.f;

    const int T = Ktot / 64;
    auto do_stage = [&](int t, int buf){
        int k0 = t * 64;
        const __half* a; int ld, ka;
        if (k0 < K1){ a = A1; ld = lda1; ka = k0; }
        else        { a = A2; ld = lda2; ka = k0 - K1; }
        uint32_t sb = smb + buf * GSTG;
        stage_tile(sb + 0,      a, ld,  row0, ka, tid);   // A, 128 rows
        stage_tile64(sb + 16384, B, ldb, col0, k0, tid);  // B, 64 rows
        cpa_commit();
    };

    do_stage(0, 0);
    for (int t = 0; t < T; t++){
        if (t + 1 < T){ do_stage(t + 1, (t + 1) & 1); cpa_wait1(); }
        else          { cpa_wait0(); }
        __syncthreads();
        uint32_t sm = smb + (t & 1) * GSTG;
        #pragma unroll
        for (int ks = 0; ks < 4; ks++){
            const int kk = ks * 16;
            uint32_t ah[2][4], bh[4][2], t4[4];
            #pragma unroll
            for (int mt = 0; mt < 2; mt++){
                uint32_t off = (uint32_t)((wm*32 + mt*16 + arow) * 128 + (kk + ak8) * 2);
                uint32_t sw = off ^ ((off >> 3) & 0x70u);
                ldsm4(ah[mt], sm + sw);
            }
            #pragma unroll
            for (int np = 0; np < 2; np++){
                uint32_t off = (uint32_t)((wn*32 + np*16 + brow) * 128 + (kk + bk8) * 2);
                uint32_t sw = off ^ ((off >> 3) & 0x70u);
                ldsm4(t4, sm + 16384 + sw);
                bh[np*2][0]=t4[0]; bh[np*2][1]=t4[1]; bh[np*2+1][0]=t4[2]; bh[np*2+1][1]=t4[3];
            }
            #pragma unroll
            for (int mt = 0; mt < 2; mt++)
                #pragma unroll
                for (int nt = 0; nt < 4; nt++)
                    mma16816(acc[mt][nt], ah[mt], bh[nt]);
        }
        __syncthreads();
    }

    const OutD& od = (blockIdx.x < split) ? o0 : o1;
    const int lq = lane >> 2, le = (lane & 3) * 2;
    #pragma unroll
    for (int mt = 0; mt < 2; mt++){
        int gr0 = row0 + wm*32 + mt*16 + lq;
        float rs0 = od.rowscale ? od.rowscale[gr0]   * od.factor : od.factor;
        float rs1 = od.rowscale ? od.rowscale[gr0+8] * od.factor : od.factor;
        #pragma unroll
        for (int nt = 0; nt < 4; nt++){
            int gc = col0 + wn*32 + nt*8 + le;
            float b0 = bias ? bias[gc] : 0.f, b1 = bias ? bias[gc+1] : 0.f;
            float v00 = (acc[mt][nt][0] + b0) * rs0, v01 = (acc[mt][nt][1] + b1) * rs0;
            float v10 = (acc[mt][nt][2] + b0) * rs1, v11 = (acc[mt][nt][3] + b1) * rs1;
            if (od.relu){
                v00 = fmaxf(v00, 0.f); v01 = fmaxf(v01, 0.f);
                v10 = fmaxf(v10, 0.f); v11 = fmaxf(v11, 0.f);
            }
            if (od.vtrans){
                int d = gc - od.colsub;
                int bidx = gr0 >> 9, kt0 = gr0 & 511;
                long long o00 = ((long long)bidx * MSG + d) * NAG + kt0;
                od.h[o00]           = __float2half_rn(v00);
                od.h[o00 + NAG]     = __float2half_rn(v01);
                od.h[o00 + 8]       = __float2half_rn(v10);
                od.h[o00 + NAG + 8] = __float2half_rn(v11);
                continue;
            }
            long long i0 = od.sC * z + (long long)gr0 * od.ldc + (gc - od.colsub);
            long long i1 = od.sC * z + (long long)(gr0 + 8) * od.ldc + (gc - od.colsub);
            if (od.f){
                *(float2*)(od.f + i0) = make_float2(v00, v01);
                *(float2*)(od.f + i1) = make_float2(v10, v11);
            }
            if (od.h){
                *(uint32_t*)(od.h + i0) = packh2(v00, v01);
                *(uint32_t*)(od.h + i1) = packh2(v10, v11);
            }
        }
    }
}

// ================= flash attention: 256 threads, V prefetched under S phase =================
__global__ __launch_bounds__(256, 1)
void flash_kernel(const __half* __restrict__ Q,   // +128 offset, ld 256
                  const __half* __restrict__ K,   // ld 128
                  const __half* __restrict__ Ob,  // obs scaled, ld 128
                  const __half* __restrict__ V,   // [b][128 d][512 k]
                  __half* __restrict__ agg)
{
    extern __shared__ __align__(1024) char smraw[];
    const uint32_t smb = smem_u32(smraw);
    const uint32_t smv = smb + 65536;
    const int tid = threadIdx.x, w = tid >> 5, lane = tid & 31;
    const int q0 = blockIdx.x * 128;
    const int b = blockIdx.y;
    const int gr = b * NAG;
    const long long vbase = (long long)b * MSG * NAG;

    const int arow = ((lane >> 3) & 1) * 8 + (lane & 7);
    const int ak8  = ((lane >> 4) & 1) * 8;
    const int brow = ((lane >> 4) & 1) * 8 + (lane & 7);
    const int bk8  = ((lane >> 3) & 1) * 8;
    const int lq = lane >> 2;

    float O[16][4];
    #pragma unroll
    for (int nt = 0; nt < 16; nt++)
        #pragma unroll
        for (int j = 0; j < 4; j++) O[nt][j] = 0.f;
    float m0 = -1e30f, m1 = -1e30f, sum0 = 0.f, sum1 = 0.f;

    for (int kt = 0; kt < 4; kt++){
        const int k0 = kt * 128;

        float S[16][4];
        #pragma unroll
        for (int nt = 0; nt < 16; nt++)
            #pragma unroll
            for (int j = 0; j < 4; j++) S[nt][j] = 0.f;

        auto do_stage = [&](int t, int buf){
            uint32_t sb = smb + buf * 32768;
            if (t < 2){
                stage_tile(sb + 0,     Q, 256, gr + q0, t*64, tid);
                stage_tile(sb + 16384, K, 128, gr + k0, t*64, tid);
            } else {
                stage_tile(sb + 0,     Ob, 128, gr + q0, (t-2)*64, tid);
                stage_tile(sb + 16384, Ob, 128, gr + k0, (t-2)*64, tid);
            }
            cpa_commit();
        };

        do_stage(0, 0);
        for (int t = 0; t < 4; t++){
            if (t == 0){
                do_stage(1, 1);
                stage_tile(smv + 0,     V + vbase, NAG, 0, k0,      tid);
                stage_tile(smv + 16384, V + vbase, NAG, 0, k0 + 64, tid);
                cpa_commit();
            } else if (t + 1 < 4){
                do_stage(t + 1, (t + 1) & 1);
            }
            if (t <= 1)      cpa_wait2();
            else if (t == 2) cpa_wait1();
            else             cpa_wait0();
            __syncthreads();
            uint32_t sm = smb + (t & 1) * 32768;
            #pragma unroll
            for (int ks = 0; ks < 4; ks++){
                const int kk = ks * 16;
                uint32_t ah[4], t4[4];
                {
                    uint32_t off = (uint32_t)((w*16 + arow) * 128 + (kk + ak8) * 2);
                    uint32_t sw = off ^ ((off >> 3) & 0x70u);
                    ldsm4(ah, sm + sw);
                }
                #pragma unroll
                for (int np = 0; np < 8; np++){
                    uint32_t off = (uint32_t)((np*16 + brow) * 128 + (kk + bk8) * 2);
                    uint32_t sw = off ^ ((off >> 3) & 0x70u);
                    ldsm4(t4, sm + 16384 + sw);
                    uint32_t b0[2] = {t4[0], t4[1]}, b1[2] = {t4[2], t4[3]};
                    mma16816(S[np*2],   ah, b0);
                    mma16816(S[np*2+1], ah, b1);
                }
            }
            __syncthreads();
        }

        // ---- online softmax ----
        float mx0 = -1e30f, mx1 = -1e30f;
        #pragma unroll
        for (int nt = 0; nt < 16; nt++){
            mx0 = fmaxf(mx0, fmaxf(S[nt][0], S[nt][1]));
            mx1 = fmaxf(mx1, fmaxf(S[nt][2], S[nt][3]));
        }
        mx0 = fmaxf(mx0, __shfl_xor_sync(0xffffffffu, mx0, 1));
        mx0 = fmaxf(mx0, __shfl_xor_sync(0xffffffffu, mx0, 2));
        mx1 = fmaxf(mx1, __shfl_xor_sync(0xffffffffu, mx1, 1));
        mx1 = fmaxf(mx1, __shfl_xor_sync(0xffffffffu, mx1, 2));
        float M0 = fmaxf(m0, mx0), M1 = fmaxf(m1, mx1);
        float f0 = __expf(m0 - M0), f1 = __expf(m1 - M1);
        float rs0 = 0.f, rs1 = 0.f;
        #pragma unroll
        for (int nt = 0; nt < 16; nt++){
            float p0 = __expf(S[nt][0] - M0); S[nt][0] = p0; rs0 += p0;
            float p1 = __expf(S[nt][1] - M0); S[nt][1] = p1; rs0 += p1;
            float p2 = __expf(S[nt][2] - M1); S[nt][2] = p2; rs1 += p2;
            float p3 = __expf(S[nt][3] - M1); S[nt][3] = p3; rs1 += p3;
        }
        rs0 += __shfl_xor_sync(0xffffffffu, rs0, 1);
        rs0 += __shfl_xor_sync(0xffffffffu, rs0, 2);
        rs1 += __shfl_xor_sync(0xffffffffu, rs1, 1);
        rs1 += __shfl_xor_sync(0xffffffffu, rs1, 2);
        sum0 = sum0 * f0 + rs0;
        sum1 = sum1 * f1 + rs1;
        m0 = M0; m1 = M1;
        #pragma unroll
        for (int nt = 0; nt < 16; nt++){
            O[nt][0] *= f0; O[nt][1] *= f0; O[nt][2] *= f1; O[nt][3] *= f1;
        }

        // ---- P·V (V resident in smv) ----
        #pragma unroll
        for (int ks = 0; ks < 8; ks++){
            uint32_t ap[4];
            ap[0] = packh2(S[2*ks][0],   S[2*ks][1]);
            ap[1] = packh2(S[2*ks][2],   S[2*ks][3]);
            ap[2] = packh2(S[2*ks+1][0], S[2*ks+1][1]);
            ap[3] = packh2(S[2*ks+1][2], S[2*ks+1][3]);
            uint32_t base = (ks < 4) ? smv : smv + 16384;
            const int kk = (ks & 3) * 16;
            #pragma unroll
            for (int np = 0; np < 8; np++){
                uint32_t off = (uint32_t)((np*16 + brow) * 128 + (kk + bk8) * 2);
                uint32_t sw = off ^ ((off >> 3) & 0x70u);
                uint32_t t4[4];
                ldsm4(t4, base + sw);
                uint32_t b0[2] = {t4[0], t4[1]}, b1[2] = {t4[2], t4[3]};
                mma16816(O[np*2],   ap, b0);
                mma16816(O[np*2+1], ap, b1);
            }
        }
        __syncthreads();
    }

    float inv0 = 1.f / sum0, inv1 = 1.f / sum1;
    long long r0 = (long long)(gr + q0 + w*16 + lq) * MSG;
    long long r1 = r0 + 8 * MSG;
    #pragma unroll
    for (int nt = 0; nt < 16; nt++){
        int d = nt*8 + (lane & 3)*2;
        *(uint32_t*)(agg + r0 + d) = packh2(O[nt][0] * inv0, O[nt][1] * inv0);
        *(uint32_t*)(agg + r1 + d) = packh2(O[nt][2] * inv1, O[nt][3] * inv1);
    }
}

// ---------------- packing kernels ----------------
__global__ void pack_obs(const float* __restrict__ obs, __half* __restrict__ h)
{
    long long i = (long long)blockIdx.x * 256 + threadIdx.x;
    h[i] = __float2half_rn(obs[i]);
}
__global__ void pack_we(const float* __restrict__ We, __half* __restrict__ hi)
{
    int i = blockIdx.x * 256 + threadIdx.x;
    int n = i >> 7, k = i & 127;
    hi[i] = __float2half_rn(We[k*256 + n]);
}
__global__ void pack_wcat(const float* __restrict__ Wc, const float* __restrict__ Wn,
                          const float* __restrict__ Wb, const float* __restrict__ Wq,
                          const float* __restrict__ bc, const float* __restrict__ bn,
                          const float* __restrict__ bbp, const float* __restrict__ bq,
                          __half* __restrict__ hi, float* __restrict__ bcat)
{
    int i = blockIdx.x * 256 + threadIdx.x;
    int n = i >> 8, k = i & 255;
    float v;
    if (n < 32)       v = Wc[k*32 + n];
    else if (n < 96)  v = Wn[k*64 + (n-32)];
    else if (n < 128) v = Wb[k*32 + (n-96)];
    else              v = Wq[k*128 + (n-128)];
    hi[i] = __float2half_rn(v);
    if (k == 0)
        bcat[n] = (n < 32) ? bc[n] : (n < 96) ? bn[n-32] : (n < 128) ? bbp[n-96] : bq[n-128];
}
__global__ void pack_wkv(const float* __restrict__ Wk, const float* __restrict__ Wv,
                         const float* __restrict__ bk, const float* __restrict__ bv,
                         __half* __restrict__ hi, float* __restrict__ bkv)
{
    int i = blockIdx.x * 256 + threadIdx.x;
    int n = i >> 7, k = i & 127;
    float v = (n < 128) ? Wk[k*128 + n] : Wv[k*128 + (n-128)];
    hi[i] = __float2half_rn(v);
    if (k == 0) bkv[n] = (n < 128) ? bk[n] : bv[n-128];
}
__global__ void pack_wp(const float* __restrict__ Wp, __half* __restrict__ hi)
{
    int i = blockIdx.x * 256 + threadIdx.x;
    int n = i / 384, k = i % 384;
    hi[i] = __float2half_rn(Wp[k*256 + n]);
}

// ---------------- importance + obs norm + scaled obs pack (fused) ----------------
__global__ void impnorm_kernel(const __half* __restrict__ enc,
                               const float* __restrict__ obs,
                               const float* __restrict__ Wi,
                               const float* __restrict__ bi,
                               float* __restrict__ imp,
                               __half* __restrict__ os)
{
    int row = blockIdx.x * 8 + threadIdx.y;
    int lane = threadIdx.x;
    const __half* e = enc + (long long)row * HID;
    const float* o = obs + (long long)row * OBS;
    float d = 0.f, ss = 0.f;
    float ov[4];
    #pragma unroll
    for (int i = 0; i < HID/32; i++){
        int k = lane + 32*i;
        d += __half2float(e[k]) * Wi[k];
    }
    #pragma unroll
    for (int i = 0; i < OBS/32; i++){ ov[i] = o[lane + 32*i]; ss += ov[i]*ov[i]; }
    #pragma unroll
    for (int off = 16; off; off >>= 1){
        d  += __shfl_xor_sync(0xffffffffu, d, off);
        ss += __shfl_xor_sync(0xffffffffu, ss, off);
    }
    if (lane == 0)
        imp[row] = 1.f / (1.f + expf(-(d + bi[0])));
    float s = 0.7071067811865476f / (sqrtf(ss) + 1e-8f);
    #pragma unroll
    for (int i = 0; i < OBS/32; i++){
        int k = lane + 32*i;
        os[(long long)row * OBS + k] = __float2half_rn(ov[i] * s);
    }
}

// ---------------- head ----------------
__global__ void head_kernel(const float* __restrict__ x,
                            const float* __restrict__ Wa,
                            const float* __restrict__ ba,
                            const float* __restrict__ Wcr,
                            const float* __restrict__ bcr,
                            float* __restrict__ out)
{
    int row = blockIdx.x * 8 + threadIdx.y;
    int lane = threadIdx.x;
    const float* xr = x + (long long)row * HID;
    float xv[8];
    #pragma unroll
    for (int i = 0; i < 8; i++) xv[i] = xr[lane + 32*i];
    #pragma unroll
    for (int j = 0; j < 17; j++){
        float p = 0.f;
        #pragma unroll
        for (int i = 0; i < 8; i++){
            int k = lane + 32*i;
            float w = (j < 16) ? Wa[(long long)k * NACT + j] : Wcr[k];
            p += xv[i] * w;
        }
        #pragma unroll
        for (int off = 16; off; off >>= 1) p += __shfl_down_sync(0xffffffffu, p, off);
        if (lane == 0){
            if (j < 16) out[(long long)row * NACT + j] = p + ba[j];
            else        out[(long long)ROWS * NACT + row] = p + bcr[0];
        }
    }
}

// ---------------- launch ----------------
extern "C" void kernel_launch(void* const* d_in, const int* in_sizes, int n_in,
                              void* d_out, int out_size)
{
    const float* obs = (const float*)d_in[0];
    const float* We  = (const float*)d_in[2];   const float* be  = (const float*)d_in[3];
    const float* Wc  = (const float*)d_in[4];   const float* bc  = (const float*)d_in[5];
    const float* Wn  = (const float*)d_in[6];   const float* bn  = (const float*)d_in[7];
    const float* Wb  = (const float*)d_in[8];   const float* bbp = (const float*)d_in[9];
    const float* Wi  = (const float*)d_in[10];  const float* bi  = (const float*)d_in[11];
    const float* Wq  = (const float*)d_in[12];  const float* bq  = (const float*)d_in[13];
    const float* Wk  = (const float*)d_in[14];  const float* bk  = (const float*)d_in[15];
    const float* Wv  = (const float*)d_in[16];  const float* bv  = (const float*)d_in[17];
    const float* Wp  = (const float*)d_in[18];  const float* bp  = (const float*)d_in[19];
    const float* Wa  = (const float*)d_in[20];  const float* ba  = (const float*)d_in[21];
    const float* Wcr = (const float*)d_in[22];  const float* bcr = (const float*)d_in[23];
    float* out = (float*)d_out;

    #define GA(p, sym) cudaGetSymbolAddress((void**)&p, sym)
    __half *enc,*msgq,*ks,*obh,*oss,*vt,*agg,*WeT,*WcT,*WkvT,*WpT;
    float *imp,*xb,*bcat,*bkv;
    GA(enc,g_enc); GA(msgq,g_msgq); GA(ks,g_ks); GA(obh,g_obs); GA(oss,g_obss);
    GA(vt,g_vT); GA(agg,g_agg); GA(imp,g_imp); GA(xb,g_x);
    GA(bcat,g_bcat); GA(bkv,g_bkv);
    GA(WeT,g_WeT); GA(WcT,g_WcatT); GA(WkvT,g_WkvT); GA(WpT,g_WpT);
    #undef GA

    cudaFuncSetAttribute(bf_gemm,      cudaFuncAttributeMaxDynamicSharedMemorySize, SMEM_GEMM);
    cudaFuncSetAttribute(flash_kernel, cudaFuncAttributeMaxDynamicSharedMemorySize, SMEM_FLASH);

    OutD z = {};

    // packs for first two gemms
    pack_obs <<<ROWS*OBS/256, 256>>>(obs, obh);
    pack_we  <<<128, 256>>>(We, WeT);
    pack_wcat<<<256, 256>>>(Wc, Wn, Wb, Wq, bc, bn, bbp, bq, WcT, bcat);

    // enc = relu(obs @ We + be) -> fp16
    {
        OutD o = z; o.h = enc; o.factor = 1.f; o.ldc = 256; o.relu = 1;
        bf_gemm<<<dim3(4,256,1), 256, SMEM_GEMM>>>(obh, OBS, OBS, nullptr, 0, OBS,
                                                   WeT, OBS, be, 0, 0, 4, o, o);
    }
    // imp + scaled obs pack (fused)
    impnorm_kernel<<<ROWS/8, dim3(32,8)>>>(enc, obs, Wi, bi, imp, oss);
    // msgq = enc @ Wcat + bcat; Q (cols>=128) scaled by imp/sqrt(128)
    {
        OutD o0 = z; o0.h = msgq; o0.factor = 1.f; o0.ldc = 256;
        OutD o1 = o0; o1.rowscale = imp; o1.factor = 0.08838834764831845f;
        bf_gemm<<<dim3(4,256,1), 256, SMEM_GEMM>>>(enc, 256, 256, nullptr, 0, 256,
                                                   WcT, 256, bcat, 0, 0, 2, o0, o1);
    }
    // pack KV weights
    pack_wkv <<<128, 256>>>(Wk, Wv, bk, bv, WkvT, bkv);
    // kv: K (cols<128) scaled by imp -> fp16; V (cols>=128) -> transposed vT
    {
        OutD o0 = z; o0.h = ks; o0.rowscale = imp; o0.factor = 1.f; o0.ldc = 128;
        OutD o1 = z; o1.h = vt; o1.factor = 1.f; o1.colsub = 128; o1.vtrans = 1;
        bf_gemm<<<dim3(4,256,1), 256, SMEM_GEMM>>>(msgq, 256, 128, nullptr, 0, 128,
                                                   WkvT, 128, bkv, 0, 0, 2, o0, o1);
    }
    // pack Wp (fills gap before flash)
    pack_wp  <<<384, 256>>>(Wp, WpT);
    // flash attention -> agg fp16
    flash_kernel<<<dim3(4, BSZ), 256, SMEM_FLASH>>>(msgq + 128, ks, oss, vt, agg);
    // x = relu([enc|agg] @ Wp + bp) -> fp32
    {
        OutD o = z; o.f = xb; o.factor = 1.f; o.ldc = 256; o.relu = 1;
        bf_gemm<<<dim3(4,256,1), 256, SMEM_GEMM>>>(enc, 256, 256, agg, 128, 384,
                                                   WpT, 384, bp, 0, 0, 4, o, o);
    }
    // heads
    head_kernel<<<ROWS/8, dim3(32,8)>>>(xb, Wa, ba, Wcr, bcr, out);
}